// round 2
// baseline (speedup 1.0000x reference)
#include <cuda_runtime.h>

// Problem constants
#define SB 8
#define SS 2048
#define SD 768
#define NORMV 0.03608439182435161f   // 1/sqrt(768)

// Scratch (allocation-free: __device__ globals)
__device__ float g_Q[SB * SS * SD];
__device__ float g_K[SB * SS * SD];
__device__ float g_V[SB * SS * SD];
__device__ float g_P[(size_t)SB * SS * SS];   // scores / probs, 134 MB

// ---------------------------------------------------------------------------
// Fused QKV projection: out = x @ W + b  (NN GEMM, M=16384, N=768, K=768)
// 128x128x8 tile, 256 threads, 8x8 per-thread micro-tile.
// blockIdx.z selects Q/K/V.
// ---------------------------------------------------------------------------
__global__ __launch_bounds__(256, 1) void proj_kernel(
    const float* __restrict__ x,
    const float* __restrict__ Wq, const float* __restrict__ bq,
    const float* __restrict__ Wk, const float* __restrict__ bk,
    const float* __restrict__ Wv, const float* __restrict__ bv)
{
    __shared__ float As[8][128];
    __shared__ float Bs[8][128];

    const int which = blockIdx.z;
    const float* __restrict__ W  = (which == 0) ? Wq : (which == 1) ? Wk : Wv;
    const float* __restrict__ bb = (which == 0) ? bq : (which == 1) ? bk : bv;
    float* outp = (which == 0) ? g_Q : (which == 1) ? g_K : g_V;

    const int tid = threadIdx.x;
    const int m0 = blockIdx.y * 128;
    const int n0 = blockIdx.x * 128;

    const int ar = tid >> 1, ac = (tid & 1) * 4;      // A loader: 128 rows x 8 k
    const int br = tid >> 5, bc = (tid & 31) * 4;     // B loader: 8 k x 128 cols
    const int ty = (tid >> 4) << 3, tx = (tid & 15) << 3;

    float acc[8][8];
#pragma unroll
    for (int i = 0; i < 8; ++i)
#pragma unroll
        for (int j = 0; j < 8; ++j) acc[i][j] = 0.f;

    const float* Ap = x + (size_t)(m0 + ar) * SD + ac;
    const float* Bp = W + (size_t)br * SD + n0 + bc;

    for (int k0 = 0; k0 < SD; k0 += 8) {
        float4 a4 = *(const float4*)(Ap + k0);
        As[ac + 0][ar] = a4.x; As[ac + 1][ar] = a4.y;
        As[ac + 2][ar] = a4.z; As[ac + 3][ar] = a4.w;
        float4 b4 = *(const float4*)(Bp + (size_t)k0 * SD);
        *(float4*)&Bs[br][bc] = b4;
        __syncthreads();
#pragma unroll
        for (int k = 0; k < 8; ++k) {
            float a[8], b[8];
            *(float4*)(a)     = *(const float4*)&As[k][ty];
            *(float4*)(a + 4) = *(const float4*)&As[k][ty + 4];
            *(float4*)(b)     = *(const float4*)&Bs[k][tx];
            *(float4*)(b + 4) = *(const float4*)&Bs[k][tx + 4];
#pragma unroll
            for (int i = 0; i < 8; ++i)
#pragma unroll
                for (int j = 0; j < 8; ++j)
                    acc[i][j] += a[i] * b[j];
        }
        __syncthreads();
    }

    float bias[8];
#pragma unroll
    for (int j = 0; j < 8; ++j) bias[j] = bb[n0 + tx + j];

    float* Cp = outp + (size_t)(m0 + ty) * SD + n0 + tx;
#pragma unroll
    for (int i = 0; i < 8; ++i) {
        float4 c0, c1;
        c0.x = acc[i][0] + bias[0]; c0.y = acc[i][1] + bias[1];
        c0.z = acc[i][2] + bias[2]; c0.w = acc[i][3] + bias[3];
        c1.x = acc[i][4] + bias[4]; c1.y = acc[i][5] + bias[5];
        c1.z = acc[i][6] + bias[6]; c1.w = acc[i][7] + bias[7];
        *(float4*)(Cp + (size_t)i * SD)     = c0;
        *(float4*)(Cp + (size_t)i * SD + 4) = c1;
    }
}

// ---------------------------------------------------------------------------
// Scores: P[b,i,j] = (Q[b,i,:] . K[b,j,:]) * mask[b,i]   (NT GEMM per batch)
// ---------------------------------------------------------------------------
__global__ __launch_bounds__(256, 1) void scores_kernel(const int* __restrict__ mask)
{
    __shared__ float As[8][128];
    __shared__ float Bs[8][128];

    const int b  = blockIdx.z;
    const int m0 = blockIdx.y * 128;   // query rows
    const int n0 = blockIdx.x * 128;   // key rows
    const int tid = threadIdx.x;

    const int ar = tid >> 1, ac = (tid & 1) * 4;
    const int ty = (tid >> 4) << 3, tx = (tid & 15) << 3;

    const float* Qb = g_Q + (size_t)b * SS * SD;
    const float* Kb = g_K + (size_t)b * SS * SD;

    const float* Ap = Qb + (size_t)(m0 + ar) * SD + ac;
    const float* Bp = Kb + (size_t)(n0 + ar) * SD + ac;   // NT: B rows are output cols

    float acc[8][8];
#pragma unroll
    for (int i = 0; i < 8; ++i)
#pragma unroll
        for (int j = 0; j < 8; ++j) acc[i][j] = 0.f;

    for (int k0 = 0; k0 < SD; k0 += 8) {
        float4 a4 = *(const float4*)(Ap + k0);
        As[ac + 0][ar] = a4.x; As[ac + 1][ar] = a4.y;
        As[ac + 2][ar] = a4.z; As[ac + 3][ar] = a4.w;
        float4 b4 = *(const float4*)(Bp + k0);
        Bs[ac + 0][ar] = b4.x; Bs[ac + 1][ar] = b4.y;
        Bs[ac + 2][ar] = b4.z; Bs[ac + 3][ar] = b4.w;
        __syncthreads();
#pragma unroll
        for (int k = 0; k < 8; ++k) {
            float a[8], bv[8];
            *(float4*)(a)      = *(const float4*)&As[k][ty];
            *(float4*)(a + 4)  = *(const float4*)&As[k][ty + 4];
            *(float4*)(bv)     = *(const float4*)&Bs[k][tx];
            *(float4*)(bv + 4) = *(const float4*)&Bs[k][tx + 4];
#pragma unroll
            for (int i = 0; i < 8; ++i)
#pragma unroll
                for (int j = 0; j < 8; ++j)
                    acc[i][j] += a[i] * bv[j];
        }
        __syncthreads();
    }

    float* Cp = g_P + (size_t)b * SS * SS + (size_t)(m0 + ty) * SS + n0 + tx;
#pragma unroll
    for (int i = 0; i < 8; ++i) {
        float mv = (float)mask[b * SS + m0 + ty + i];
        float4 c0, c1;
        c0.x = acc[i][0] * mv; c0.y = acc[i][1] * mv;
        c0.z = acc[i][2] * mv; c0.w = acc[i][3] * mv;
        c1.x = acc[i][4] * mv; c1.y = acc[i][5] * mv;
        c1.z = acc[i][6] * mv; c1.w = acc[i][7] * mv;
        *(float4*)(Cp + (size_t)i * SS)     = c0;
        *(float4*)(Cp + (size_t)i * SS + 4) = c1;
    }
}

// ---------------------------------------------------------------------------
// Row softmax over 2048 keys, then scale by NORM (post-softmax, per reference).
// One block per row; row cached in smem (8 KB) so global traffic = 1R + 1W.
// A fully-zero masked row naturally yields uniform 1/2048 — matches reference.
// ---------------------------------------------------------------------------
__global__ __launch_bounds__(256, 1) void softmax_kernel()
{
    __shared__ float row[SS];
    __shared__ float red[256];
    const int r = blockIdx.x;                 // 0 .. B*S-1
    float* p = g_P + (size_t)r * SS;
    const int tid = threadIdx.x;

    float m = -3.4e38f;
    for (int i = tid; i < SS; i += 256) { float v = p[i]; row[i] = v; m = fmaxf(m, v); }
    red[tid] = m;
    __syncthreads();
    for (int s = 128; s > 0; s >>= 1) {
        if (tid < s) red[tid] = fmaxf(red[tid], red[tid + s]);
        __syncthreads();
    }
    m = red[0];
    __syncthreads();

    float sum = 0.f;
    for (int i = tid; i < SS; i += 256) { float e = __expf(row[i] - m); row[i] = e; sum += e; }
    red[tid] = sum;
    __syncthreads();
    for (int s = 128; s > 0; s >>= 1) {
        if (tid < s) red[tid] += red[tid + s];
        __syncthreads();
    }
    const float inv = NORMV / red[0];
    for (int i = tid; i < SS; i += 256) p[i] = row[i] * inv;
}

// ---------------------------------------------------------------------------
// Output: out[b] = P[b] @ V[b]   (NN GEMM per batch, M=2048, N=768, K=2048)
// ---------------------------------------------------------------------------
__global__ __launch_bounds__(256, 1) void out_kernel(float* __restrict__ out)
{
    __shared__ float As[8][128];
    __shared__ float Bs[8][128];

    const int b  = blockIdx.z;
    const int m0 = blockIdx.y * 128;
    const int n0 = blockIdx.x * 128;
    const int tid = threadIdx.x;

    const int ar = tid >> 1, ac = (tid & 1) * 4;
    const int br = tid >> 5, bc = (tid & 31) * 4;
    const int ty = (tid >> 4) << 3, tx = (tid & 15) << 3;

    const float* A  = g_P + (size_t)b * SS * SS;
    const float* Bm = g_V + (size_t)b * SS * SD;

    const float* Ap = A + (size_t)(m0 + ar) * SS + ac;
    const float* Bp = Bm + (size_t)br * SD + n0 + bc;

    float acc[8][8];
#pragma unroll
    for (int i = 0; i < 8; ++i)
#pragma unroll
        for (int j = 0; j < 8; ++j) acc[i][j] = 0.f;

    for (int k0 = 0; k0 < SS; k0 += 8) {
        float4 a4 = *(const float4*)(Ap + k0);
        As[ac + 0][ar] = a4.x; As[ac + 1][ar] = a4.y;
        As[ac + 2][ar] = a4.z; As[ac + 3][ar] = a4.w;
        float4 b4 = *(const float4*)(Bp + (size_t)k0 * SD);
        *(float4*)&Bs[br][bc] = b4;
        __syncthreads();
#pragma unroll
        for (int k = 0; k < 8; ++k) {
            float a[8], bv[8];
            *(float4*)(a)      = *(const float4*)&As[k][ty];
            *(float4*)(a + 4)  = *(const float4*)&As[k][ty + 4];
            *(float4*)(bv)     = *(const float4*)&Bs[k][tx];
            *(float4*)(bv + 4) = *(const float4*)&Bs[k][tx + 4];
#pragma unroll
            for (int i = 0; i < 8; ++i)
#pragma unroll
                for (int j = 0; j < 8; ++j)
                    acc[i][j] += a[i] * bv[j];
        }
        __syncthreads();
    }

    float* Cp = out + (size_t)b * SS * SD + (size_t)(m0 + ty) * SD + n0 + tx;
#pragma unroll
    for (int i = 0; i < 8; ++i) {
        float4 c0, c1;
        c0.x = acc[i][0]; c0.y = acc[i][1]; c0.z = acc[i][2]; c0.w = acc[i][3];
        c1.x = acc[i][4]; c1.y = acc[i][5]; c1.z = acc[i][6]; c1.w = acc[i][7];
        *(float4*)(Cp + (size_t)i * SD)     = c0;
        *(float4*)(Cp + (size_t)i * SD + 4) = c1;
    }
}

// ---------------------------------------------------------------------------
// Launch. Inputs (metadata order): x, mask, Wq, bq, Wk, bk, Wv, bv.
// ---------------------------------------------------------------------------
extern "C" void kernel_launch(void* const* d_in, const int* in_sizes, int n_in,
                              void* d_out, int out_size)
{
    const float* x    = (const float*)d_in[0];
    const int*   mask = (const int*)  d_in[1];
    const float* Wq   = (const float*)d_in[2];
    const float* bq   = (const float*)d_in[3];
    const float* Wk   = (const float*)d_in[4];
    const float* bk   = (const float*)d_in[5];
    const float* Wv   = (const float*)d_in[6];
    const float* bv   = (const float*)d_in[7];
    float* out = (float*)d_out;

    // QKV projection: M=16384 (128 blocks), N=768 (6 blocks), z = {Q,K,V}
    proj_kernel<<<dim3(6, 128, 3), 256>>>(x, Wq, bq, Wk, bk, Wv, bv);
    // Scores: per batch 16x16 tiles of 128x128
    scores_kernel<<<dim3(16, 16, SB), 256>>>(mask);
    // Softmax: one block per (b, query row)
    softmax_kernel<<<SB * SS, 256>>>();
    // Output GEMM: per batch, M=2048 (16 blocks), N=768 (6 blocks)
    out_kernel<<<dim3(6, 16, SB), 256>>>(out);
}

// round 6
// speedup vs baseline: 2.5880x; 2.5880x over previous
#include <cuda_runtime.h>
#include <cuda_bf16.h>
#include <cstdint>

#define SB 8
#define SS 2048
#define SD 768
#define NORMV 0.03608439182435161f   // 1/sqrt(768)

typedef __nv_bfloat16 bf16;

// ----------------------------- scratch (device globals, allocation-free) ----
__device__ bf16 g_xhi[SB * SS * SD], g_xlo[SB * SS * SD];
__device__ bf16 g_Wthi[3 * SD * SD], g_Wtlo[3 * SD * SD];     // W transposed [n][k]
__device__ bf16 g_Qhi[SB * SS * SD], g_Qlo[SB * SS * SD];
__device__ bf16 g_Khi[SB * SS * SD], g_Klo[SB * SS * SD];
__device__ bf16 g_Vthi[SB * SD * SS], g_Vtlo[SB * SD * SS];   // V transposed [b][n][t]
__device__ float g_P[(size_t)SB * SS * SS];                   // fp32 scores
__device__ bf16 g_Phi[(size_t)SB * SS * SS], g_Plo[(size_t)SB * SS * SS];

// ----------------------------- PTX helpers ---------------------------------
__device__ __forceinline__ uint32_t smem_u32(const void* p) {
    uint32_t a;
    asm("{ .reg .u64 t; cvta.to.shared.u64 t, %1; cvt.u32.u64 %0, t; }" : "=r"(a) : "l"(p));
    return a;
}
__device__ __forceinline__ void cpa16(uint32_t s, const void* g) {
    asm volatile("cp.async.cg.shared.global [%0], [%1], 16;" :: "r"(s), "l"(g));
}
__device__ __forceinline__ void cp_commit() { asm volatile("cp.async.commit_group;" ::: "memory"); }
template <int N> __device__ __forceinline__ void cp_wait() {
    asm volatile("cp.async.wait_group %0;" :: "n"(N) : "memory");
}
__device__ __forceinline__ void ldsm4(uint32_t addr, uint32_t* r) {
    asm volatile("ldmatrix.sync.aligned.m8n8.x4.shared.b16 {%0,%1,%2,%3}, [%4];"
                 : "=r"(r[0]), "=r"(r[1]), "=r"(r[2]), "=r"(r[3]) : "r"(addr));
}
__device__ __forceinline__ void mma16816(float* c, const uint32_t* a, const uint32_t* b) {
    asm volatile(
        "mma.sync.aligned.m16n8k16.row.col.f32.bf16.bf16.f32 "
        "{%0,%1,%2,%3}, {%4,%5,%6,%7}, {%8,%9}, {%0,%1,%2,%3};"
        : "+f"(c[0]), "+f"(c[1]), "+f"(c[2]), "+f"(c[3])
        : "r"(a[0]), "r"(a[1]), "r"(a[2]), "r"(a[3]), "r"(b[0]), "r"(b[1]));
}
// swizzled 16B-segment address within a 128-row x 128B tile
__device__ __forceinline__ uint32_t sw_addr(uint32_t tilebase, int row, int seg) {
    return tilebase + (uint32_t)(row * 128 + (((seg) ^ (row & 7)) << 4));
}

// ----------------------------- tile loader ---------------------------------
// Stage layout: Ah @ +0, Al @ +16384, Bh @ +32768, Bl @ +49152 (each 128x64 bf16)
__device__ __forceinline__ void load_stage(uint32_t tiles, int buf,
    const bf16* __restrict__ Ah, const bf16* __restrict__ Al,
    const bf16* __restrict__ Bh, const bf16* __restrict__ Bl,
    int lda, int ldb, int rowA0, int rowB0, int k0, int tid)
{
    uint32_t tb = tiles + buf * 65536;
#pragma unroll
    for (int c = 0; c < 4; ++c) {
        int idx = tid + c * 256;          // 0..1023 : 128 rows x 8 x 16B
        int row = idx >> 3, seg = idx & 7;
        uint32_t soff = (uint32_t)(row * 128 + (((seg) ^ (row & 7)) << 4));
        size_t aoff = (size_t)(rowA0 + row) * lda + k0 + seg * 8;
        size_t boff = (size_t)(rowB0 + row) * ldb + k0 + seg * 8;
        cpa16(tb + soff,         Ah + aoff);
        cpa16(tb + 16384 + soff, Al + aoff);
        cpa16(tb + 32768 + soff, Bh + boff);
        cpa16(tb + 49152 + soff, Bl + boff);
    }
    cp_commit();
}

// ----------------------------- GEMM kernel ---------------------------------
// D[128x128] = A[128xK] . B[128xK]^T  (both K-major), 3-term bf16 hi/lo split.
// MODE 0: Q proj   1: K proj   2: V proj (transposed epilogue)
// MODE 3: scores (mask, fp32 P)   4: out (P @ V^T -> d_out)
template <int MODE>
__global__ void __launch_bounds__(256, 1) gemm_kernel(
    const float* __restrict__ bias, const int* __restrict__ mask, float* __restrict__ outF)
{
    constexpr int KLEN = (MODE == 4) ? SS : SD;
    constexpr int NS = KLEN / 64;

    extern __shared__ char dsm[];
    uint32_t tiles = (smem_u32(dsm) + 127) & ~127u;

    const int tid = threadIdx.x, wid = tid >> 5, lane = tid & 31;
    const int wm = wid & 3, wn = wid >> 2;           // 4x2 warp grid
    const int bz = blockIdx.z;
    const int rowA0 = blockIdx.y * 128, rowB0 = blockIdx.x * 128;

    const bf16 *Ah, *Al, *Bh, *Bl;
    int lda, ldb;
    if constexpr (MODE <= 2) {
        Ah = g_xhi; Al = g_xlo;
        Bh = g_Wthi + MODE * SD * SD; Bl = g_Wtlo + MODE * SD * SD;
        lda = SD; ldb = SD;
    } else if constexpr (MODE == 3) {
        Ah = g_Qhi + (size_t)bz * SS * SD; Al = g_Qlo + (size_t)bz * SS * SD;
        Bh = g_Khi + (size_t)bz * SS * SD; Bl = g_Klo + (size_t)bz * SS * SD;
        lda = SD; ldb = SD;
    } else {
        Ah = g_Phi + (size_t)bz * SS * SS; Al = g_Plo + (size_t)bz * SS * SS;
        Bh = g_Vthi + (size_t)bz * SD * SS; Bl = g_Vtlo + (size_t)bz * SD * SS;
        lda = SS; ldb = SS;
    }

    float c[2][8][4];
#pragma unroll
    for (int i = 0; i < 2; ++i)
#pragma unroll
        for (int j = 0; j < 8; ++j)
#pragma unroll
            for (int k = 0; k < 4; ++k) c[i][j][k] = 0.f;

    // prologue: fill 3 stages
    load_stage(tiles, 0, Ah, Al, Bh, Bl, lda, ldb, rowA0, rowB0, 0,   tid);
    load_stage(tiles, 1, Ah, Al, Bh, Bl, lda, ldb, rowA0, rowB0, 64,  tid);
    load_stage(tiles, 2, Ah, Al, Bh, Bl, lda, ldb, rowA0, rowB0, 128, tid);

    const int lr = lane & 15, lk = lane >> 4;    // ldmatrix row / k-half select

    int buf = 0;
    for (int s = 0; s < NS; ++s) {
        cp_wait<2>();
        __syncthreads();
        uint32_t tb = tiles + buf * 65536;

#pragma unroll
        for (int kk = 0; kk < 4; ++kk) {
            const int seg = 2 * kk + lk;
            // A fragments (hi & lo), 2 m16 tiles
            uint32_t ah[2][4], al[2][4];
#pragma unroll
            for (int mi = 0; mi < 2; ++mi) {
                int arow = wm * 32 + mi * 16 + lr;
                ldsm4(sw_addr(tb,         arow, seg), ah[mi]);
                ldsm4(sw_addr(tb + 16384, arow, seg), al[mi]);
            }
            // B fragments (hi & lo), 8 n8 tiles via 4 x4 loads per term
            uint32_t bh[8][2], bl[8][2];
#pragma unroll
            for (int nj = 0; nj < 4; ++nj) {
                int brow = wn * 64 + nj * 16 + lr;
                uint32_t r[4];
                ldsm4(sw_addr(tb + 32768, brow, seg), r);
                bh[2 * nj][0] = r[0]; bh[2 * nj][1] = r[2];
                bh[2 * nj + 1][0] = r[1]; bh[2 * nj + 1][1] = r[3];
                ldsm4(sw_addr(tb + 49152, brow, seg), r);
                bl[2 * nj][0] = r[0]; bl[2 * nj][1] = r[2];
                bl[2 * nj + 1][0] = r[1]; bl[2 * nj + 1][1] = r[3];
            }
#pragma unroll
            for (int mi = 0; mi < 2; ++mi)
#pragma unroll
                for (int ni = 0; ni < 8; ++ni) {
                    mma16816(c[mi][ni], ah[mi], bh[ni]);
                    mma16816(c[mi][ni], ah[mi], bl[ni]);
                    mma16816(c[mi][ni], al[mi], bh[ni]);
                }
        }
        __syncthreads();
        if (s + 3 < NS)
            load_stage(tiles, buf, Ah, Al, Bh, Bl, lda, ldb, rowA0, rowB0, (s + 3) * 64, tid);
        buf = (buf == 2) ? 0 : buf + 1;
    }

    // ---------------- epilogue ------------------------------------------
    const int qr = lane >> 2, qc = 2 * (lane & 3);
#pragma unroll
    for (int mi = 0; mi < 2; ++mi) {
#pragma unroll
        for (int half = 0; half < 2; ++half) {
            const int row = rowA0 + wm * 32 + mi * 16 + qr + 8 * half;
#pragma unroll
            for (int ni = 0; ni < 8; ++ni) {
                const int col = rowB0 + wn * 64 + ni * 8 + qc;
                float v0 = c[mi][ni][2 * half], v1 = c[mi][ni][2 * half + 1];

                if constexpr (MODE == 0 || MODE == 1) {
                    bf16* oh = (MODE == 0) ? g_Qhi : g_Khi;
                    bf16* ol = (MODE == 0) ? g_Qlo : g_Klo;
                    v0 += bias[col]; v1 += bias[col + 1];
                    bf16 h0 = __float2bfloat16(v0), h1 = __float2bfloat16(v1);
                    bf16 l0 = __float2bfloat16(v0 - __bfloat162float(h0));
                    bf16 l1 = __float2bfloat16(v1 - __bfloat162float(h1));
                    size_t o = (size_t)row * SD + col;
                    *reinterpret_cast<__nv_bfloat162*>(&oh[o]) = __halves2bfloat162(h0, h1);
                    *reinterpret_cast<__nv_bfloat162*>(&ol[o]) = __halves2bfloat162(l0, l1);
                } else if constexpr (MODE == 2) {      // V -> V^T hi/lo
                    const int b = row >> 11, t = row & (SS - 1);
                    v0 += bias[col]; v1 += bias[col + 1];
                    bf16 h0 = __float2bfloat16(v0), h1 = __float2bfloat16(v1);
                    size_t o0 = ((size_t)b * SD + col) * SS + t;
                    size_t o1 = ((size_t)b * SD + col + 1) * SS + t;
                    g_Vthi[o0] = h0;
                    g_Vtlo[o0] = __float2bfloat16(v0 - __bfloat162float(h0));
                    g_Vthi[o1] = h1;
                    g_Vtlo[o1] = __float2bfloat16(v1 - __bfloat162float(h1));
                } else if constexpr (MODE == 3) {      // scores * mask(row)
                    float mv = (float)mask[bz * SS + row];
                    float2 v = make_float2(v0 * mv, v1 * mv);
                    *reinterpret_cast<float2*>(
                        g_P + (size_t)bz * SS * SS + (size_t)row * SS + col) = v;
                } else {                                // final fp32 out
                    *reinterpret_cast<float2*>(
                        outF + ((size_t)bz * SS + row) * SD + col) = make_float2(v0, v1);
                }
            }
        }
    }
}

// ----------------------------- prep / softmax kernels ----------------------
__global__ void split_x_kernel(const float* __restrict__ x) {
    for (size_t i = (size_t)blockIdx.x * blockDim.x + threadIdx.x;
         i < (size_t)SB * SS * SD; i += (size_t)gridDim.x * blockDim.x) {
        float v = x[i];
        bf16 h = __float2bfloat16(v);
        g_xhi[i] = h;
        g_xlo[i] = __float2bfloat16(v - __bfloat162float(h));
    }
}

__global__ void wsplit_kernel(const float* __restrict__ Wq,
                              const float* __restrict__ Wk,
                              const float* __restrict__ Wv) {
    __shared__ float ts[32][33];
    const float* W = (blockIdx.z == 0) ? Wq : (blockIdx.z == 1) ? Wk : Wv;
    bf16* oh = g_Wthi + blockIdx.z * SD * SD;
    bf16* ol = g_Wtlo + blockIdx.z * SD * SD;
    int n0 = blockIdx.x * 32, k0 = blockIdx.y * 32;
    int tx = threadIdx.x, ty = threadIdx.y;
    for (int i = ty; i < 32; i += 8) ts[i][tx] = W[(size_t)(k0 + i) * SD + n0 + tx];
    __syncthreads();
    for (int i = ty; i < 32; i += 8) {
        float v = ts[tx][i];                // = W[k0+tx][n0+i]
        bf16 h = __float2bfloat16(v);
        size_t o = (size_t)(n0 + i) * SD + k0 + tx;   // Wt[n][k]
        oh[o] = h;
        ol[o] = __float2bfloat16(v - __bfloat162float(h));
    }
}

__global__ void __launch_bounds__(256, 1) softmax_kernel() {
    __shared__ float rowv[SS];
    __shared__ float red[256];
    const size_t r = blockIdx.x;
    const float* p = g_P + r * SS;
    const int tid = threadIdx.x;

    float m = -3.4e38f;
    for (int i = tid; i < SS; i += 256) { float v = p[i]; rowv[i] = v; m = fmaxf(m, v); }
    red[tid] = m; __syncthreads();
    for (int s = 128; s > 0; s >>= 1) { if (tid < s) red[tid] = fmaxf(red[tid], red[tid + s]); __syncthreads(); }
    m = red[0]; __syncthreads();

    float sum = 0.f;
    for (int i = tid; i < SS; i += 256) { float e = __expf(rowv[i] - m); rowv[i] = e; sum += e; }
    red[tid] = sum; __syncthreads();
    for (int s = 128; s > 0; s >>= 1) { if (tid < s) red[tid] += red[tid + s]; __syncthreads(); }
    const float inv = NORMV / red[0];

    for (int i = tid; i < SS; i += 256) {
        float v = rowv[i] * inv;
        bf16 h = __float2bfloat16(v);
        g_Phi[r * SS + i] = h;
        g_Plo[r * SS + i] = __float2bfloat16(v - __bfloat162float(h));
    }
}

// ----------------------------- launch --------------------------------------
extern "C" void kernel_launch(void* const* d_in, const int* in_sizes, int n_in,
                              void* d_out, int out_size)
{
    const float* x    = (const float*)d_in[0];
    const int*   mask = (const int*)  d_in[1];
    const float* Wq   = (const float*)d_in[2];
    const float* bq   = (const float*)d_in[3];
    const float* Wk   = (const float*)d_in[4];
    const float* bk   = (const float*)d_in[5];
    const float* Wv   = (const float*)d_in[6];
    const float* bv   = (const float*)d_in[7];
    float* out = (float*)d_out;

    const int smem = 196736;   // 3 stages x 64KB + align slack
    cudaFuncSetAttribute(gemm_kernel<0>, cudaFuncAttributeMaxDynamicSharedMemorySize, smem);
    cudaFuncSetAttribute(gemm_kernel<1>, cudaFuncAttributeMaxDynamicSharedMemorySize, smem);
    cudaFuncSetAttribute(gemm_kernel<2>, cudaFuncAttributeMaxDynamicSharedMemorySize, smem);
    cudaFuncSetAttribute(gemm_kernel<3>, cudaFuncAttributeMaxDynamicSharedMemorySize, smem);
    cudaFuncSetAttribute(gemm_kernel<4>, cudaFuncAttributeMaxDynamicSharedMemorySize, smem);

    split_x_kernel<<<4096, 256>>>(x);
    wsplit_kernel<<<dim3(24, 24, 3), dim3(32, 8)>>>(Wq, Wk, Wv);

    gemm_kernel<0><<<dim3(6, 128, 1), 256, smem>>>(bq, nullptr, nullptr);    // Q
    gemm_kernel<1><<<dim3(6, 128, 1), 256, smem>>>(bk, nullptr, nullptr);    // K
    gemm_kernel<2><<<dim3(6, 128, 1), 256, smem>>>(bv, nullptr, nullptr);    // V -> V^T
    gemm_kernel<3><<<dim3(16, 16, SB), 256, smem>>>(nullptr, mask, nullptr); // scores
    softmax_kernel<<<SB * SS, 256>>>();
    gemm_kernel<4><<<dim3(6, 16, SB), 256, smem>>>(nullptr, nullptr, out);   // P @ V^T
}